// round 9
// baseline (speedup 1.0000x reference)
#include <cuda_runtime.h>
#include <cuda_fp16.h>
#include <cstdint>

#define NNODES 100000
#define NEDGES 1600000
#define NB     391                     // ceil(NNODES/256)
#define NF4    (NNODES * 16)           // float4 slots per fp32 plane
#define PCSR   (NEDGES + 3 * NNODES)   // padded CSR capacity (pad to mult of 4)
#define NBINS  64

// ---------------------------------------------------------------------------
// Device-global scratch (no allocation allowed).
__device__ __half2 g_feat[4][NNODES * 32];        // planes 0..3 fp16
__device__ __align__(16) int2 g_csr[PCSR];        // {src, bits(dis[src])}, padded
__device__ int     g_off[NNODES + 1];             // padded offsets (mult of 4)
__device__ int     g_cursor[NNODES];
__device__ int     g_deg[NNODES];
__device__ float   g_dis[NNODES];
__device__ int     g_order[NNODES];               // degree-bucketed node order
__device__ int     g_binh[NBINS];
__device__ int     g_bincur[NBINS];
__device__ int     g_blocksum[512];
__device__ int     g_blockoff[512];
__device__ int     g_idx64;

// ---------------------------------------------------------------------------
// detect index width (block 0 warp 0) + zero deg + zero bin histogram
__global__ void detect_zerodeg_kernel(const int* __restrict__ ei32) {
    int i = blockIdx.x * blockDim.x + threadIdx.x;
    if (i < NNODES) g_deg[i] = 0;
    if (i < NBINS) g_binh[i] = 0;
    if (blockIdx.x == 0 && threadIdx.x < 32) {
        int lane = threadIdx.x;
        int nz = 0;
        for (int q = lane; q < 2048; q += 32) nz |= ei32[2 * q + 1];
        unsigned m = __ballot_sync(0xffffffffu, nz != 0);
        if (lane == 0) g_idx64 = (m == 0) ? 1 : 0;
    }
}

// deg atomic (edge e) + feat0 init (float4 slot e) — both ranges are 1.6M
__global__ void deg_init_kernel(const void* __restrict__ eiv,
                                const float4* __restrict__ x4) {
    int e = blockIdx.x * blockDim.x + threadIdx.x;
    if (e >= NEDGES) return;
    int d;
    if (g_idx64) d = (int)((const long long*)eiv)[NEDGES + e];
    else         d = ((const int*)eiv)[NEDGES + e];
    atomicAdd(&g_deg[d], 1);

    float4 v = x4[e];
    g_feat[0][2 * e]     = __floats2half2_rn(v.x, v.y);
    g_feat[0][2 * e + 1] = __floats2half2_rn(v.z, v.w);
}

// ---------------------------------------------------------------------------
// exclusive scan of padded degrees pdeg = (deg+3)&~3
__global__ void partial_kernel() {
    __shared__ int s[256];
    int i = blockIdx.x * 256 + threadIdx.x;
    int v = (i < NNODES) ? ((g_deg[i] + 3) & ~3) : 0;
    s[threadIdx.x] = v; __syncthreads();
    for (int st = 128; st > 0; st >>= 1) {
        if (threadIdx.x < st) s[threadIdx.x] += s[threadIdx.x + st];
        __syncthreads();
    }
    if (threadIdx.x == 0) g_blocksum[blockIdx.x] = s[0];
}

__global__ void scanblock_kernel() {
    __shared__ int s[512];
    int t = threadIdx.x;
    int v = (t < NB) ? g_blocksum[t] : 0;
    s[t] = v; __syncthreads();
    for (int st = 1; st < 512; st <<= 1) {
        int add = (t >= st) ? s[t - st] : 0;
        __syncthreads();
        s[t] += add;
        __syncthreads();
    }
    if (t < NB) g_blockoff[t] = s[t] - v;   // exclusive
}

// offsets (padded), cursor, dis, CSR pad entries, bin histogram
__global__ void offsets_dis_kernel() {
    __shared__ int s[256];
    int i = blockIdx.x * 256 + threadIdx.x;
    int deg  = (i < NNODES) ? g_deg[i] : 0;
    int pdeg = (deg + 3) & ~3;
    s[threadIdx.x] = pdeg; __syncthreads();
    for (int st = 1; st < 256; st <<= 1) {
        int add = (threadIdx.x >= st) ? s[threadIdx.x - st] : 0;
        __syncthreads();
        s[threadIdx.x] += add;
        __syncthreads();
    }
    int off = g_blockoff[blockIdx.x] + s[threadIdx.x] - pdeg;  // exclusive
    if (i < NNODES) {
        g_off[i] = off;
        g_cursor[i] = off;
        g_dis[i] = rsqrtf(fmaxf((float)deg, 1.0f));
        // pad entries: src=0, w=0
        for (int j = deg; j < pdeg; j++) g_csr[off + j] = make_int2(0, 0);
        int bin = pdeg >> 2; if (bin > NBINS - 1) bin = NBINS - 1;
        atomicAdd(&g_binh[bin], 1);
    }
    if (i == NNODES - 1) g_off[NNODES] = off + pdeg;
}

// suffix-sum bin offsets (descending bin order: biggest trip counts first)
__global__ void binscan_kernel() {
    __shared__ int c[NBINS];
    int t = threadIdx.x;
    c[t] = g_binh[t];
    __syncthreads();
    int off = 0;
    for (int b = t + 1; b < NBINS; b++) off += c[b];
    g_bincur[t] = off;
}

__global__ void order_kernel() {
    int i = blockIdx.x * blockDim.x + threadIdx.x;
    if (i >= NNODES) return;
    int pdeg = (g_deg[i] + 3) & ~3;
    int bin = pdeg >> 2; if (bin > NBINS - 1) bin = NBINS - 1;
    int pos = atomicAdd(&g_bincur[bin], 1);
    g_order[pos] = i;
}

// fill CSR: pos = cursor[dst]++ ; csr[pos] = {src, bits(dis[src])}
__global__ void fill_kernel(const void* __restrict__ eiv) {
    int e = blockIdx.x * blockDim.x + threadIdx.x;
    if (e >= NEDGES) return;
    int s, d;
    if (g_idx64) {
        const long long* p = (const long long*)eiv;
        s = (int)p[e]; d = (int)p[NEDGES + e];
    } else {
        const int* p = (const int*)eiv;
        s = p[e]; d = p[NEDGES + e];
    }
    int pos = atomicAdd(&g_cursor[d], 1);
    g_csr[pos] = make_int2(s, __float_as_int(g_dis[s]));
}

// ---------------------------------------------------------------------------
// gather core: 8 lanes/node, 16 B/lane, uniform 4-edge bodies (padded CSR),
// csr read as 2 aligned int4; MLP = 4 row LDG.128 + 2 csr LDG.128.
__device__ __forceinline__ void acc_row(float2& a0, float2& a1, float2& a2, float2& a3,
                                        float w, uint4 r) {
    float2 f0 = __half22float2(*reinterpret_cast<__half2*>(&r.x));
    float2 f1 = __half22float2(*reinterpret_cast<__half2*>(&r.y));
    float2 f2 = __half22float2(*reinterpret_cast<__half2*>(&r.z));
    float2 f3 = __half22float2(*reinterpret_cast<__half2*>(&r.w));
    a0.x = fmaf(w, f0.x, a0.x); a0.y = fmaf(w, f0.y, a0.y);
    a1.x = fmaf(w, f1.x, a1.x); a1.y = fmaf(w, f1.y, a1.y);
    a2.x = fmaf(w, f2.x, a2.x); a2.y = fmaf(w, f2.y, a2.y);
    a3.x = fmaf(w, f3.x, a3.x); a3.y = fmaf(w, f3.y, a3.y);
}

__device__ __forceinline__ void gather_accum(int node, int sl,
                                             const uint4* __restrict__ fp,
                                             float2& a0, float2& a1,
                                             float2& a2, float2& a3) {
    int beg = __ldg(&g_off[node]), end = __ldg(&g_off[node + 1]);
    a0 = {0.f, 0.f}; a1 = {0.f, 0.f}; a2 = {0.f, 0.f}; a3 = {0.f, 0.f};

    const int4* c4 = reinterpret_cast<const int4*>(g_csr);
    for (int j = beg; j < end; j += 4) {
        int4 c0 = __ldg(&c4[(j >> 1)]);       // edges j, j+1
        int4 c1 = __ldg(&c4[(j >> 1) + 1]);   // edges j+2, j+3
        uint4 r0 = __ldg(&fp[c0.x * 8 + sl]);
        uint4 r1 = __ldg(&fp[c0.z * 8 + sl]);
        uint4 r2 = __ldg(&fp[c1.x * 8 + sl]);
        uint4 r3 = __ldg(&fp[c1.z * 8 + sl]);
        acc_row(a0, a1, a2, a3, __int_as_float(c0.y), r0);
        acc_row(a0, a1, a2, a3, __int_as_float(c0.w), r1);
        acc_row(a0, a1, a2, a3, __int_as_float(c1.y), r2);
        acc_row(a0, a1, a2, a3, __int_as_float(c1.w), r3);
    }
}

// iterations k = 1..3: feat_k = feat_{k-1} - dis*agg  (fp16 store)
__global__ void gather_kernel(int k) {
    int t = blockIdx.x * blockDim.x + threadIdx.x;
    int ni = t >> 3;
    if (ni >= NNODES) return;
    int node = __ldg(&g_order[ni]);
    int sl = t & 7;

    const uint4* fp = reinterpret_cast<const uint4*>(g_feat[k - 1]);
    uint4*       fn = reinterpret_cast<uint4*>(g_feat[k]);

    float2 a0, a1, a2, a3;
    gather_accum(node, sl, fp, a0, a1, a2, a3);

    float disn = g_dis[node];
    uint4 own = fp[node * 8 + sl];
    float2 f0 = __half22float2(*reinterpret_cast<__half2*>(&own.x));
    float2 f1 = __half22float2(*reinterpret_cast<__half2*>(&own.y));
    float2 f2 = __half22float2(*reinterpret_cast<__half2*>(&own.z));
    float2 f3 = __half22float2(*reinterpret_cast<__half2*>(&own.w));

    __half2 o0 = __floats2half2_rn(f0.x - disn * a0.x, f0.y - disn * a0.y);
    __half2 o1 = __floats2half2_rn(f1.x - disn * a1.x, f1.y - disn * a1.y);
    __half2 o2 = __floats2half2_rn(f2.x - disn * a2.x, f2.y - disn * a2.y);
    __half2 o3 = __floats2half2_rn(f3.x - disn * a3.x, f3.y - disn * a3.y);

    uint4 out;
    out.x = *reinterpret_cast<unsigned*>(&o0);
    out.y = *reinterpret_cast<unsigned*>(&o1);
    out.z = *reinterpret_cast<unsigned*>(&o2);
    out.w = *reinterpret_cast<unsigned*>(&o3);
    fn[node * 8 + sl] = out;
}

// iteration k = 4 fused with the polynomial combine:
// out = 0.6*x - 0.4*f1 + 0.3*f2 - 0.2*f3 + 0.1*(f3 - dis*agg)
__global__ void gather_final_kernel(const float4* __restrict__ x4,
                                    float4* __restrict__ out4) {
    int t = blockIdx.x * blockDim.x + threadIdx.x;
    int ni = t >> 3;
    if (ni >= NNODES) return;
    int node = __ldg(&g_order[ni]);
    int sl = t & 7;

    const uint4* fp3 = reinterpret_cast<const uint4*>(g_feat[3]);

    float2 a0, a1, a2, a3;
    gather_accum(node, sl, fp3, a0, a1, a2, a3);

    float disn = g_dis[node];
    int ri = node * 8 + sl;

    uint4 r3 = fp3[ri];
    uint4 r1 = reinterpret_cast<const uint4*>(g_feat[1])[ri];
    uint4 r2 = reinterpret_cast<const uint4*>(g_feat[2])[ri];

    float agg[8] = {a0.x, a0.y, a1.x, a1.y, a2.x, a2.y, a3.x, a3.y};
    unsigned w3[4] = {r3.x, r3.y, r3.z, r3.w};
    unsigned w1[4] = {r1.x, r1.y, r1.z, r1.w};
    unsigned w2[4] = {r2.x, r2.y, r2.z, r2.w};

    float4 xv0 = __ldg(&x4[node * 16 + sl * 2]);
    float4 xv1 = __ldg(&x4[node * 16 + sl * 2 + 1]);
    float xs[8] = {xv0.x, xv0.y, xv0.z, xv0.w, xv1.x, xv1.y, xv1.z, xv1.w};

    float os[8];
#pragma unroll
    for (int q = 0; q < 4; q++) {
        float2 f3v = __half22float2(*reinterpret_cast<__half2*>(&w3[q]));
        float2 f1v = __half22float2(*reinterpret_cast<__half2*>(&w1[q]));
        float2 f2v = __half22float2(*reinterpret_cast<__half2*>(&w2[q]));
        float f4x = f3v.x - disn * agg[2 * q];
        float f4y = f3v.y - disn * agg[2 * q + 1];
        os[2 * q]     = fmaf(0.1f, f4x, fmaf(-0.2f, f3v.x,
                        fmaf(0.3f, f2v.x, fmaf(-0.4f, f1v.x, 0.6f * xs[2 * q]))));
        os[2 * q + 1] = fmaf(0.1f, f4y, fmaf(-0.2f, f3v.y,
                        fmaf(0.3f, f2v.y, fmaf(-0.4f, f1v.y, 0.6f * xs[2 * q + 1]))));
    }
    float4 o0 = {os[0], os[1], os[2], os[3]};
    float4 o1 = {os[4], os[5], os[6], os[7]};
    out4[node * 16 + sl * 2]     = o0;
    out4[node * 16 + sl * 2 + 1] = o1;
}

// ---------------------------------------------------------------------------
extern "C" void kernel_launch(void* const* d_in, const int* in_sizes, int n_in,
                              void* d_out, int out_size) {
    const float4* x4 = (const float4*)d_in[0];
    const void*   ei = d_in[1];

    detect_zerodeg_kernel<<<NB, 256>>>((const int*)ei);
    deg_init_kernel<<<(NEDGES + 255) / 256, 256>>>(ei, x4);
    partial_kernel<<<NB, 256>>>();
    scanblock_kernel<<<1, 512>>>();
    offsets_dis_kernel<<<NB, 256>>>();
    binscan_kernel<<<1, NBINS>>>();
    order_kernel<<<NB, 256>>>();
    fill_kernel<<<(NEDGES + 255) / 256, 256>>>(ei);

    const int gthreads = NNODES * 8;
    const int gblocks = (gthreads + 255) / 256;
    for (int k = 1; k <= 3; k++)
        gather_kernel<<<gblocks, 256>>>(k);
    gather_final_kernel<<<gblocks, 256>>>(x4, (float4*)d_out);
}

// round 10
// speedup vs baseline: 1.0070x; 1.0070x over previous
#include <cuda_runtime.h>
#include <cuda_fp16.h>
#include <cstdint>

#define NNODES 100000
#define NEDGES 1600000
#define NB     391            // ceil(NNODES/256)
#define NF4    (NNODES * 16)  // float4 slots per fp32 plane (== NEDGES)
#define NBINS  256

// ---------------------------------------------------------------------------
// Device-global scratch (no allocation allowed). All per-node arrays used by
// the gather hot loop live in RANK space (degree-descending order).
__device__ __half2 g_feat[4][NNODES * 32];   // planes 0..3 fp16, RANK space
__device__ int2    g_csr[NEDGES];            // {src_rank, bits(dis[src])}
__device__ int     g_off[NNODES + 1];        // RANK space
__device__ int     g_cursor[NNODES];         // RANK space
__device__ float   g_disr[NNODES];           // RANK space
__device__ int     g_deg[NNODES];            // node space
__device__ float   g_disn[NNODES];           // node space
__device__ int     g_order[NNODES];          // rank -> node
__device__ int     g_rank[NNODES];           // node -> rank
__device__ int     g_binh[NBINS];
__device__ int     g_bincur[NBINS];
__device__ int     g_blocksum[512];
__device__ int     g_blockoff[512];
__device__ int     g_idx64;

// ---------------------------------------------------------------------------
// detect index width + zero deg + zero bin histogram
__global__ void detect_zero_kernel(const int* __restrict__ ei32) {
    int i = blockIdx.x * blockDim.x + threadIdx.x;
    if (i < NNODES) g_deg[i] = 0;
    if (i < NBINS) g_binh[i] = 0;
    if (blockIdx.x == 0 && threadIdx.x < 32) {
        int lane = threadIdx.x;
        int nz = 0;
        for (int q = lane; q < 2048; q += 32) nz |= ei32[2 * q + 1];
        unsigned m = __ballot_sync(0xffffffffu, nz != 0);
        if (lane == 0) g_idx64 = (m == 0) ? 1 : 0;
    }
}

__global__ void deg_kernel(const void* __restrict__ eiv) {
    int e = blockIdx.x * blockDim.x + threadIdx.x;
    if (e >= NEDGES) return;
    int d;
    if (g_idx64) d = (int)((const long long*)eiv)[NEDGES + e];
    else         d = ((const int*)eiv)[NEDGES + e];
    atomicAdd(&g_deg[d], 1);
}

// histogram by degree (capped) + node-space dis
__global__ void hist_kernel() {
    int i = blockIdx.x * blockDim.x + threadIdx.x;
    if (i >= NNODES) return;
    int deg = g_deg[i];
    g_disn[i] = rsqrtf(fmaxf((float)deg, 1.0f));
    int bin = deg < NBINS ? deg : NBINS - 1;
    atomicAdd(&g_binh[bin], 1);
}

// descending-degree bin bases: bincur[b] = #nodes with deg-bin > b
__global__ void binscan_kernel() {
    __shared__ int c[NBINS];
    int t = threadIdx.x;
    c[t] = g_binh[t];
    __syncthreads();
    int off = 0;
    for (int b = t + 1; b < NBINS; b++) off += c[b];
    g_bincur[t] = off;
}

__global__ void order_kernel() {
    int i = blockIdx.x * blockDim.x + threadIdx.x;
    if (i >= NNODES) return;
    int deg = g_deg[i];
    int bin = deg < NBINS ? deg : NBINS - 1;
    int r = atomicAdd(&g_bincur[bin], 1);
    g_order[r] = i;
    g_rank[i] = r;
}

// ---------------------------------------------------------------------------
// exclusive scan of rank-ordered degrees -> g_off / g_cursor / g_disr
__global__ void partial_kernel() {
    __shared__ int s[256];
    int i = blockIdx.x * 256 + threadIdx.x;
    int v = (i < NNODES) ? g_deg[g_order[i]] : 0;
    s[threadIdx.x] = v; __syncthreads();
    for (int st = 128; st > 0; st >>= 1) {
        if (threadIdx.x < st) s[threadIdx.x] += s[threadIdx.x + st];
        __syncthreads();
    }
    if (threadIdx.x == 0) g_blocksum[blockIdx.x] = s[0];
}

__global__ void scanblock_kernel() {
    __shared__ int s[512];
    int t = threadIdx.x;
    int v = (t < NB) ? g_blocksum[t] : 0;
    s[t] = v; __syncthreads();
    for (int st = 1; st < 512; st <<= 1) {
        int add = (t >= st) ? s[t - st] : 0;
        __syncthreads();
        s[t] += add;
        __syncthreads();
    }
    if (t < NB) g_blockoff[t] = s[t] - v;   // exclusive
}

__global__ void offsets_kernel() {
    __shared__ int s[256];
    int i = blockIdx.x * 256 + threadIdx.x;
    int node = (i < NNODES) ? g_order[i] : 0;
    int v = (i < NNODES) ? g_deg[node] : 0;
    s[threadIdx.x] = v; __syncthreads();
    for (int st = 1; st < 256; st <<= 1) {
        int add = (threadIdx.x >= st) ? s[threadIdx.x - st] : 0;
        __syncthreads();
        s[threadIdx.x] += add;
        __syncthreads();
    }
    int off = g_blockoff[blockIdx.x] + s[threadIdx.x] - v;  // exclusive
    if (i < NNODES) {
        g_off[i] = off;
        g_cursor[i] = off;
        g_disr[i] = rsqrtf(fmaxf((float)v, 1.0f));
    }
    if (i == NNODES - 1) g_off[NNODES] = off + v;
}

// fill CSR in rank space: pos = cursor[rank[dst]]++ ; entry = {rank[src], dis_n[src]}
__global__ void fill_kernel(const void* __restrict__ eiv) {
    int e = blockIdx.x * blockDim.x + threadIdx.x;
    if (e >= NEDGES) return;
    int s, d;
    if (g_idx64) {
        const long long* p = (const long long*)eiv;
        s = (int)p[e]; d = (int)p[NEDGES + e];
    } else {
        const int* p = (const int*)eiv;
        s = p[e]; d = p[NEDGES + e];
    }
    int pos = atomicAdd(&g_cursor[g_rank[d]], 1);
    g_csr[pos] = make_int2(g_rank[s], __float_as_int(g_disn[s]));
}

// init feat0 in rank space: feat0[rank[node] row] = half(x[node row])
__global__ void init_kernel(const float4* __restrict__ x4) {
    int i = blockIdx.x * blockDim.x + threadIdx.x;
    if (i >= NF4) return;
    int node = i >> 4, slot = i & 15;
    int di = g_rank[node] * 16 + slot;
    float4 v = x4[i];
    g_feat[0][2 * di]     = __floats2half2_rn(v.x, v.y);
    g_feat[0][2 * di + 1] = __floats2half2_rn(v.z, v.w);
}

// ---------------------------------------------------------------------------
// R8-proven gather core: 8 lanes/node, lane owns 16 B of the row; per-thread
// 4-wide unroll -> MLP>=4 independent LDG.128s. All indices are ranks.
__device__ __forceinline__ void acc_row(float2& a0, float2& a1, float2& a2, float2& a3,
                                        float w, uint4 r) {
    float2 f0 = __half22float2(*reinterpret_cast<__half2*>(&r.x));
    float2 f1 = __half22float2(*reinterpret_cast<__half2*>(&r.y));
    float2 f2 = __half22float2(*reinterpret_cast<__half2*>(&r.z));
    float2 f3 = __half22float2(*reinterpret_cast<__half2*>(&r.w));
    a0.x = fmaf(w, f0.x, a0.x); a0.y = fmaf(w, f0.y, a0.y);
    a1.x = fmaf(w, f1.x, a1.x); a1.y = fmaf(w, f1.y, a1.y);
    a2.x = fmaf(w, f2.x, a2.x); a2.y = fmaf(w, f2.y, a2.y);
    a3.x = fmaf(w, f3.x, a3.x); a3.y = fmaf(w, f3.y, a3.y);
}

__device__ __forceinline__ void gather_accum(int rank, int sl,
                                             const uint4* __restrict__ fp,
                                             float2& a0, float2& a1,
                                             float2& a2, float2& a3) {
    int beg = __ldg(&g_off[rank]), end = __ldg(&g_off[rank + 1]);
    a0 = {0.f, 0.f}; a1 = {0.f, 0.f}; a2 = {0.f, 0.f}; a3 = {0.f, 0.f};

    int j = beg;
    for (; j + 4 <= end; j += 4) {
        int2 e0 = __ldg(&g_csr[j]);
        int2 e1 = __ldg(&g_csr[j + 1]);
        int2 e2 = __ldg(&g_csr[j + 2]);
        int2 e3 = __ldg(&g_csr[j + 3]);
        uint4 r0 = __ldg(&fp[e0.x * 8 + sl]);
        uint4 r1 = __ldg(&fp[e1.x * 8 + sl]);
        uint4 r2 = __ldg(&fp[e2.x * 8 + sl]);
        uint4 r3 = __ldg(&fp[e3.x * 8 + sl]);
        acc_row(a0, a1, a2, a3, __int_as_float(e0.y), r0);
        acc_row(a0, a1, a2, a3, __int_as_float(e1.y), r1);
        acc_row(a0, a1, a2, a3, __int_as_float(e2.y), r2);
        acc_row(a0, a1, a2, a3, __int_as_float(e3.y), r3);
    }
    for (; j < end; j++) {
        int2 e0 = __ldg(&g_csr[j]);
        uint4 r0 = __ldg(&fp[e0.x * 8 + sl]);
        acc_row(a0, a1, a2, a3, __int_as_float(e0.y), r0);
    }
}

// iterations k = 1..3: feat_k = feat_{k-1} - dis*agg  (fp16 store, rank space)
__global__ void gather_kernel(int k) {
    int t = blockIdx.x * blockDim.x + threadIdx.x;
    int rank = t >> 3;
    if (rank >= NNODES) return;
    int sl = t & 7;

    const uint4* fp = reinterpret_cast<const uint4*>(g_feat[k - 1]);
    uint4*       fn = reinterpret_cast<uint4*>(g_feat[k]);

    float2 a0, a1, a2, a3;
    gather_accum(rank, sl, fp, a0, a1, a2, a3);

    float disn = __ldg(&g_disr[rank]);
    uint4 own = fp[rank * 8 + sl];
    float2 f0 = __half22float2(*reinterpret_cast<__half2*>(&own.x));
    float2 f1 = __half22float2(*reinterpret_cast<__half2*>(&own.y));
    float2 f2 = __half22float2(*reinterpret_cast<__half2*>(&own.z));
    float2 f3 = __half22float2(*reinterpret_cast<__half2*>(&own.w));

    __half2 o0 = __floats2half2_rn(f0.x - disn * a0.x, f0.y - disn * a0.y);
    __half2 o1 = __floats2half2_rn(f1.x - disn * a1.x, f1.y - disn * a1.y);
    __half2 o2 = __floats2half2_rn(f2.x - disn * a2.x, f2.y - disn * a2.y);
    __half2 o3 = __floats2half2_rn(f3.x - disn * a3.x, f3.y - disn * a3.y);

    uint4 out;
    out.x = *reinterpret_cast<unsigned*>(&o0);
    out.y = *reinterpret_cast<unsigned*>(&o1);
    out.z = *reinterpret_cast<unsigned*>(&o2);
    out.w = *reinterpret_cast<unsigned*>(&o3);
    fn[rank * 8 + sl] = out;
}

// iteration k = 4 fused with the polynomial combine (x read / out write in
// original node space via g_order):
// out = 0.6*x - 0.4*f1 + 0.3*f2 - 0.2*f3 + 0.1*(f3 - dis*agg)
__global__ void gather_final_kernel(const float4* __restrict__ x4,
                                    float4* __restrict__ out4) {
    int t = blockIdx.x * blockDim.x + threadIdx.x;
    int rank = t >> 3;
    if (rank >= NNODES) return;
    int sl = t & 7;

    const uint4* fp3 = reinterpret_cast<const uint4*>(g_feat[3]);

    float2 a0, a1, a2, a3;
    gather_accum(rank, sl, fp3, a0, a1, a2, a3);

    float disn = __ldg(&g_disr[rank]);
    int ri = rank * 8 + sl;

    uint4 r3 = fp3[ri];
    uint4 r1 = reinterpret_cast<const uint4*>(g_feat[1])[ri];
    uint4 r2 = reinterpret_cast<const uint4*>(g_feat[2])[ri];

    float agg[8] = {a0.x, a0.y, a1.x, a1.y, a2.x, a2.y, a3.x, a3.y};
    unsigned w3[4] = {r3.x, r3.y, r3.z, r3.w};
    unsigned w1[4] = {r1.x, r1.y, r1.z, r1.w};
    unsigned w2[4] = {r2.x, r2.y, r2.z, r2.w};

    int node = __ldg(&g_order[rank]);
    float4 xv0 = __ldg(&x4[node * 16 + sl * 2]);
    float4 xv1 = __ldg(&x4[node * 16 + sl * 2 + 1]);
    float xs[8] = {xv0.x, xv0.y, xv0.z, xv0.w, xv1.x, xv1.y, xv1.z, xv1.w};

    float os[8];
#pragma unroll
    for (int q = 0; q < 4; q++) {
        float2 f3v = __half22float2(*reinterpret_cast<__half2*>(&w3[q]));
        float2 f1v = __half22float2(*reinterpret_cast<__half2*>(&w1[q]));
        float2 f2v = __half22float2(*reinterpret_cast<__half2*>(&w2[q]));
        float f4x = f3v.x - disn * agg[2 * q];
        float f4y = f3v.y - disn * agg[2 * q + 1];
        os[2 * q]     = fmaf(0.1f, f4x, fmaf(-0.2f, f3v.x,
                        fmaf(0.3f, f2v.x, fmaf(-0.4f, f1v.x, 0.6f * xs[2 * q]))));
        os[2 * q + 1] = fmaf(0.1f, f4y, fmaf(-0.2f, f3v.y,
                        fmaf(0.3f, f2v.y, fmaf(-0.4f, f1v.y, 0.6f * xs[2 * q + 1]))));
    }
    float4 o0 = {os[0], os[1], os[2], os[3]};
    float4 o1 = {os[4], os[5], os[6], os[7]};
    out4[node * 16 + sl * 2]     = o0;
    out4[node * 16 + sl * 2 + 1] = o1;
}

// ---------------------------------------------------------------------------
extern "C" void kernel_launch(void* const* d_in, const int* in_sizes, int n_in,
                              void* d_out, int out_size) {
    const float4* x4 = (const float4*)d_in[0];
    const void*   ei = d_in[1];

    detect_zero_kernel<<<NB, 256>>>((const int*)ei);
    deg_kernel<<<(NEDGES + 255) / 256, 256>>>(ei);
    hist_kernel<<<NB, 256>>>();
    binscan_kernel<<<1, NBINS>>>();
    order_kernel<<<NB, 256>>>();
    partial_kernel<<<NB, 256>>>();
    scanblock_kernel<<<1, 512>>>();
    offsets_kernel<<<NB, 256>>>();
    fill_kernel<<<(NEDGES + 255) / 256, 256>>>(ei);
    init_kernel<<<(NF4 + 255) / 256, 256>>>(x4);

    const int gthreads = NNODES * 8;
    const int gblocks = (gthreads + 255) / 256;
    for (int k = 1; k <= 3; k++)
        gather_kernel<<<gblocks, 256>>>(k);
    gather_final_kernel<<<gblocks, 256>>>(x4, (float4*)d_out);
}

// round 11
// speedup vs baseline: 1.2971x; 1.2882x over previous
#include <cuda_runtime.h>
#include <cuda_fp16.h>
#include <cstdint>

#define NNODES 100000
#define NEDGES 1600000
#define NB     391                    // ceil(NNODES/256)
#define NF4    (NNODES * 16)          // float4 slots per fp32 plane (== NEDGES)
#define PCSR   (NEDGES + 3 * NNODES)  // padded CSR capacity
#define NROWS  (NNODES + 1)           // +1 zero row for dummy edges
#define NBLK   196                    // scan blocks: 196*512 >= NNODES

// ---------------------------------------------------------------------------
// Device-global scratch (no allocation allowed). Planes store S_k = dis*feat_k.
__device__ __half2 g_feat[4][NROWS * 32];     // planes 0..3 fp16 (row NNODES = 0)
__device__ __align__(16) int g_csr[PCSR];     // src index only; pads = NNODES
__device__ int     g_off[NNODES + 1];         // padded offsets (mult of 4)
__device__ int     g_cursor[NNODES];
__device__ int     g_deg[NNODES];
__device__ float   g_dis[NNODES];             // 1/sqrt(max(deg,1))
__device__ float   g_dis2[NNODES];            // 1/max(deg,1)
__device__ float   g_invdis[NNODES];          // sqrt(max(deg,1))
__device__ unsigned long long g_state[NBLK];  // lookback: flag<<62 | sum
__device__ unsigned g_ticket;
__device__ int     g_idx64;

// ---------------------------------------------------------------------------
// zero deg / scan state / ticket / zero-rows + detect index width
__global__ void detect_zero_kernel(const int* __restrict__ ei32) {
    int i = blockIdx.x * blockDim.x + threadIdx.x;
    if (i < NNODES) g_deg[i] = 0;
    if (i < NBLK) g_state[i] = 0ULL;
    if (i == NNODES) g_ticket = 0;
    if (i < 128) {  // zero row NNODES of all 4 planes (4 planes x 32 half2)
        int plane = i >> 5, slot = i & 31;
        g_feat[plane][NNODES * 32 + slot] = __floats2half2_rn(0.f, 0.f);
    }
    if (blockIdx.x == 0 && threadIdx.x < 32) {
        int lane = threadIdx.x;
        int nz = 0;
        for (int q = lane; q < 2048; q += 32) nz |= ei32[2 * q + 1];
        unsigned m = __ballot_sync(0xffffffffu, nz != 0);
        if (lane == 0) g_idx64 = (m == 0) ? 1 : 0;
    }
}

__global__ void deg_kernel(const void* __restrict__ eiv) {
    int e = blockIdx.x * blockDim.x + threadIdx.x;
    if (e >= NEDGES) return;
    int d;
    if (g_idx64) d = (int)((const long long*)eiv)[NEDGES + e];
    else         d = ((const int*)eiv)[NEDGES + e];
    atomicAdd(&g_deg[d], 1);
}

// ---------------------------------------------------------------------------
// Single-pass decoupled-lookback exclusive scan of padded degrees.
// Also writes cursor, dis/dis2/invdis, and the CSR pad entries (= NNODES).
__global__ void scan_kernel() {
    __shared__ int s[512];
    __shared__ int sbid, sexcl;
    int tid = threadIdx.x;
    if (tid == 0) sbid = (int)atomicAdd(&g_ticket, 1u);
    __syncthreads();
    int bid = sbid;
    int i = bid * 512 + tid;

    int deg  = (i < NNODES) ? g_deg[i] : 0;
    int pdeg = (deg + 3) & ~3;

    s[tid] = pdeg; __syncthreads();
    for (int st = 1; st < 512; st <<= 1) {
        int a = (tid >= st) ? s[tid - st] : 0;
        __syncthreads();
        s[tid] += a;
        __syncthreads();
    }
    int incl = s[tid], total = s[511];

    if (tid == 0) {
        if (bid == 0) {
            atomicExch(&g_state[0], (2ULL << 62) | (unsigned)total);
            sexcl = 0;
        } else {
            atomicExch(&g_state[bid], (1ULL << 62) | (unsigned)total);
            long long ex = 0; int p = bid - 1;
            while (true) {
                unsigned long long v = atomicAdd(&g_state[p], 0ULL);
                unsigned long long fl = v >> 62;
                if (fl == 2ULL) { ex += (long long)(v & 0xFFFFFFFFULL); break; }
                if (fl == 1ULL) { ex += (long long)(v & 0xFFFFFFFFULL); p--; }
            }
            atomicExch(&g_state[bid], (2ULL << 62) | (unsigned)(ex + total));
            sexcl = (int)ex;
        }
    }
    __syncthreads();

    int off = sexcl + incl - pdeg;   // exclusive, multiple of 4
    if (i < NNODES) {
        g_off[i] = off;
        g_cursor[i] = off;
        float fd = fmaxf((float)deg, 1.0f);
        g_dis[i] = rsqrtf(fd);
        g_dis2[i] = 1.0f / fd;
        g_invdis[i] = sqrtf(fd);
        for (int j = deg; j < pdeg; j++) g_csr[off + j] = NNODES;  // dummy -> zero row
    }
    if (i == NNODES - 1) g_off[NNODES] = off + pdeg;
}

// ---------------------------------------------------------------------------
// fill CSR (edge e) + init S0 = dis*x (float4 slot e) — both ranges are 1.6M
__global__ void fill_init_kernel(const void* __restrict__ eiv,
                                 const float4* __restrict__ x4) {
    int e = blockIdx.x * blockDim.x + threadIdx.x;
    if (e >= NEDGES) return;
    int s, d;
    if (g_idx64) {
        const long long* p = (const long long*)eiv;
        s = (int)p[e]; d = (int)p[NEDGES + e];
    } else {
        const int* p = (const int*)eiv;
        s = p[e]; d = p[NEDGES + e];
    }
    int pos = atomicAdd(&g_cursor[d], 1);
    g_csr[pos] = s;

    int node = e >> 4;
    float dis = g_dis[node];
    float4 v = x4[e];
    g_feat[0][2 * e]     = __floats2half2_rn(dis * v.x, dis * v.y);
    g_feat[0][2 * e + 1] = __floats2half2_rn(dis * v.z, dis * v.w);
}

// ---------------------------------------------------------------------------
// Gather core (R8 skeleton): 8 lanes/node, 16 B/lane, uniform 4-edge bodies,
// one aligned LDG.128 for 4 src indices, 4 independent row LDG.128s (MLP>=4).
__device__ __forceinline__ void acc_row(float2& a0, float2& a1, float2& a2, float2& a3,
                                        uint4 r) {
    float2 f0 = __half22float2(*reinterpret_cast<__half2*>(&r.x));
    float2 f1 = __half22float2(*reinterpret_cast<__half2*>(&r.y));
    float2 f2 = __half22float2(*reinterpret_cast<__half2*>(&r.z));
    float2 f3 = __half22float2(*reinterpret_cast<__half2*>(&r.w));
    a0.x += f0.x; a0.y += f0.y;
    a1.x += f1.x; a1.y += f1.y;
    a2.x += f2.x; a2.y += f2.y;
    a3.x += f3.x; a3.y += f3.y;
}

__device__ __forceinline__ void gather_accum(int node, int sl,
                                             const uint4* __restrict__ fp,
                                             float2& a0, float2& a1,
                                             float2& a2, float2& a3) {
    int beg = __ldg(&g_off[node]), end = __ldg(&g_off[node + 1]);
    a0 = {0.f, 0.f}; a1 = {0.f, 0.f}; a2 = {0.f, 0.f}; a3 = {0.f, 0.f};

    const int4* c4 = reinterpret_cast<const int4*>(g_csr);
    for (int j = beg; j < end; j += 4) {
        int4 c = __ldg(&c4[j >> 2]);
        uint4 r0 = __ldg(&fp[c.x * 8 + sl]);
        uint4 r1 = __ldg(&fp[c.y * 8 + sl]);
        uint4 r2 = __ldg(&fp[c.z * 8 + sl]);
        uint4 r3 = __ldg(&fp[c.w * 8 + sl]);
        acc_row(a0, a1, a2, a3, r0);
        acc_row(a0, a1, a2, a3, r1);
        acc_row(a0, a1, a2, a3, r2);
        acc_row(a0, a1, a2, a3, r3);
    }
}

// iterations k = 1..3: S_k = S_{k-1} - dis^2 * agg   (fp16 store)
__global__ void gather_kernel(int k) {
    int t = blockIdx.x * blockDim.x + threadIdx.x;
    int node = t >> 3;
    if (node >= NNODES) return;
    int sl = t & 7;

    const uint4* fp = reinterpret_cast<const uint4*>(g_feat[k - 1]);
    uint4*       fn = reinterpret_cast<uint4*>(g_feat[k]);

    float2 a0, a1, a2, a3;
    gather_accum(node, sl, fp, a0, a1, a2, a3);

    float d2 = __ldg(&g_dis2[node]);
    uint4 own = fp[node * 8 + sl];
    float2 f0 = __half22float2(*reinterpret_cast<__half2*>(&own.x));
    float2 f1 = __half22float2(*reinterpret_cast<__half2*>(&own.y));
    float2 f2 = __half22float2(*reinterpret_cast<__half2*>(&own.z));
    float2 f3 = __half22float2(*reinterpret_cast<__half2*>(&own.w));

    __half2 o0 = __floats2half2_rn(f0.x - d2 * a0.x, f0.y - d2 * a0.y);
    __half2 o1 = __floats2half2_rn(f1.x - d2 * a1.x, f1.y - d2 * a1.y);
    __half2 o2 = __floats2half2_rn(f2.x - d2 * a2.x, f2.y - d2 * a2.y);
    __half2 o3 = __floats2half2_rn(f3.x - d2 * a3.x, f3.y - d2 * a3.y);

    uint4 out;
    out.x = *reinterpret_cast<unsigned*>(&o0);
    out.y = *reinterpret_cast<unsigned*>(&o1);
    out.z = *reinterpret_cast<unsigned*>(&o2);
    out.w = *reinterpret_cast<unsigned*>(&o3);
    fn[node * 8 + sl] = out;
}

// iteration k = 4 fused with the polynomial combine:
// out = 0.6*x + invdis * (-0.4*S1 + 0.3*S2 - 0.2*S3 + 0.1*S4),
// S4 = S3 - dis^2 * agg
__global__ void gather_final_kernel(const float4* __restrict__ x4,
                                    float4* __restrict__ out4) {
    int t = blockIdx.x * blockDim.x + threadIdx.x;
    int node = t >> 3;
    if (node >= NNODES) return;
    int sl = t & 7;

    const uint4* fp3 = reinterpret_cast<const uint4*>(g_feat[3]);

    float2 a0, a1, a2, a3;
    gather_accum(node, sl, fp3, a0, a1, a2, a3);

    float d2 = __ldg(&g_dis2[node]);
    float inv = __ldg(&g_invdis[node]);
    int ri = node * 8 + sl;

    uint4 r3 = fp3[ri];
    uint4 r1 = reinterpret_cast<const uint4*>(g_feat[1])[ri];
    uint4 r2 = reinterpret_cast<const uint4*>(g_feat[2])[ri];

    float agg[8] = {a0.x, a0.y, a1.x, a1.y, a2.x, a2.y, a3.x, a3.y};
    unsigned w3[4] = {r3.x, r3.y, r3.z, r3.w};
    unsigned w1[4] = {r1.x, r1.y, r1.z, r1.w};
    unsigned w2[4] = {r2.x, r2.y, r2.z, r2.w};

    float4 xv0 = __ldg(&x4[node * 16 + sl * 2]);
    float4 xv1 = __ldg(&x4[node * 16 + sl * 2 + 1]);
    float xs[8] = {xv0.x, xv0.y, xv0.z, xv0.w, xv1.x, xv1.y, xv1.z, xv1.w};

    float os[8];
#pragma unroll
    for (int q = 0; q < 4; q++) {
        float2 s3 = __half22float2(*reinterpret_cast<__half2*>(&w3[q]));
        float2 s1 = __half22float2(*reinterpret_cast<__half2*>(&w1[q]));
        float2 s2 = __half22float2(*reinterpret_cast<__half2*>(&w2[q]));
        float s4x = s3.x - d2 * agg[2 * q];
        float s4y = s3.y - d2 * agg[2 * q + 1];
        float px = fmaf(0.1f, s4x, fmaf(-0.2f, s3.x, fmaf(0.3f, s2.x, -0.4f * s1.x)));
        float py = fmaf(0.1f, s4y, fmaf(-0.2f, s3.y, fmaf(0.3f, s2.y, -0.4f * s1.y)));
        os[2 * q]     = fmaf(inv, px, 0.6f * xs[2 * q]);
        os[2 * q + 1] = fmaf(inv, py, 0.6f * xs[2 * q + 1]);
    }
    float4 o0 = {os[0], os[1], os[2], os[3]};
    float4 o1 = {os[4], os[5], os[6], os[7]};
    out4[node * 16 + sl * 2]     = o0;
    out4[node * 16 + sl * 2 + 1] = o1;
}

// ---------------------------------------------------------------------------
extern "C" void kernel_launch(void* const* d_in, const int* in_sizes, int n_in,
                              void* d_out, int out_size) {
    const float4* x4 = (const float4*)d_in[0];
    const void*   ei = d_in[1];

    detect_zero_kernel<<<NB, 256>>>((const int*)ei);
    deg_kernel<<<(NEDGES + 255) / 256, 256>>>(ei);
    scan_kernel<<<NBLK, 512>>>();
    fill_init_kernel<<<(NEDGES + 255) / 256, 256>>>(ei, x4);

    const int gthreads = NNODES * 8;
    const int gblocks = (gthreads + 255) / 256;
    for (int k = 1; k <= 3; k++)
        gather_kernel<<<gblocks, 256>>>(k);
    gather_final_kernel<<<gblocks, 256>>>(x4, (float4*)d_out);
}

// round 14
// speedup vs baseline: 1.3125x; 1.0119x over previous
#include <cuda_runtime.h>
#include <cuda_fp16.h>
#include <cstdint>

#define NNODES 100000
#define NEDGES 1600000
#define NF4    (NNODES * 16)          // float4 slots per fp32 plane (== NEDGES)
#define PCSR   (NEDGES + 3 * NNODES)  // padded CSR capacity
#define NROWS  (NNODES + 1)           // +1 zero row for dummy edges
#define NBLK   196                    // scan blocks: 196*512 >= NNODES

// ---------------------------------------------------------------------------
// Device-global scratch (no allocation allowed). Planes store S_k = dis*feat_k.
// Invariant: g_deg is all-zero on entry to kernel_launch (zero at load; scan
// re-zeroes after consuming).
__device__ __half2 g_feat[4][NROWS * 32];     // planes 0..3 fp16 (row NNODES = 0)
__device__ __align__(16) int g_csr[PCSR];     // src index only; pads = NNODES
__device__ int     g_off[NNODES + 1];         // padded offsets (mult of 4)
__device__ int     g_cursor[NNODES];
__device__ int     g_deg[NNODES];
__device__ float   g_dis[NNODES];             // 1/sqrt(max(deg,1))
__device__ float   g_dis2[NNODES];            // 1/max(deg,1)
__device__ float   g_invdis[NNODES];          // sqrt(max(deg,1))
__device__ unsigned long long g_state[NBLK];  // lookback: flag<<62 | sum
__device__ unsigned g_ticket;
__device__ int     g_idx64;

// ---------------------------------------------------------------------------
// single tiny block: detect index width, zero scan state/ticket, zero row NNODES
__global__ void detect_kernel(const int* __restrict__ ei32) {
    int t = threadIdx.x;
    if (t < NBLK) g_state[t] = 0ULL;
    if (t == 255) g_ticket = 0;
    if (t < 128) {  // zero row NNODES of all 4 planes (4 planes x 32 half2)
        int plane = t >> 5, slot = t & 31;
        g_feat[plane][NNODES * 32 + slot] = __floats2half2_rn(0.f, 0.f);
    }
    if (t < 32) {
        int nz = 0;
        for (int q = t; q < 2048; q += 32) nz |= ei32[2 * q + 1];
        unsigned m = __ballot_sync(0xffffffffu, nz != 0);
        if (t == 0) g_idx64 = (m == 0) ? 1 : 0;
    }
}

__global__ void deg_kernel(const void* __restrict__ eiv) {
    int e = blockIdx.x * blockDim.x + threadIdx.x;
    if (e >= NEDGES) return;
    int d;
    if (g_idx64) d = (int)((const long long*)eiv)[NEDGES + e];
    else         d = ((const int*)eiv)[NEDGES + e];
    atomicAdd(&g_deg[d], 1);
}

// ---------------------------------------------------------------------------
// Single-pass decoupled-lookback exclusive scan of padded degrees.
// Writes cursor, dis/dis2/invdis, CSR pad entries; re-zeroes g_deg.
__global__ void scan_kernel() {
    __shared__ int s[512];
    __shared__ int sbid, sexcl;
    int tid = threadIdx.x;
    if (tid == 0) sbid = (int)atomicAdd(&g_ticket, 1u);
    __syncthreads();
    int bid = sbid;
    int i = bid * 512 + tid;

    int deg  = (i < NNODES) ? g_deg[i] : 0;
    int pdeg = (deg + 3) & ~3;

    s[tid] = pdeg; __syncthreads();
    for (int st = 1; st < 512; st <<= 1) {
        int a = (tid >= st) ? s[tid - st] : 0;
        __syncthreads();
        s[tid] += a;
        __syncthreads();
    }
    int incl = s[tid], total = s[511];

    if (tid == 0) {
        if (bid == 0) {
            atomicExch(&g_state[0], (2ULL << 62) | (unsigned)total);
            sexcl = 0;
        } else {
            atomicExch(&g_state[bid], (1ULL << 62) | (unsigned)total);
            long long ex = 0; int p = bid - 1;
            while (true) {
                unsigned long long v = atomicAdd(&g_state[p], 0ULL);
                unsigned long long fl = v >> 62;
                if (fl == 2ULL) { ex += (long long)(v & 0xFFFFFFFFULL); break; }
                if (fl == 1ULL) { ex += (long long)(v & 0xFFFFFFFFULL); p--; }
            }
            atomicExch(&g_state[bid], (2ULL << 62) | (unsigned)(ex + total));
            sexcl = (int)ex;
        }
    }
    __syncthreads();

    int off = sexcl + incl - pdeg;   // exclusive, multiple of 4
    if (i < NNODES) {
        g_off[i] = off;
        g_cursor[i] = off;
        float fd = fmaxf((float)deg, 1.0f);
        g_dis[i] = rsqrtf(fd);
        g_dis2[i] = 1.0f / fd;
        g_invdis[i] = sqrtf(fd);
        for (int j = deg; j < pdeg; j++) g_csr[off + j] = NNODES;  // dummy -> zero row
        g_deg[i] = 0;   // restore invariant for next replay
    }
    if (i == NNODES - 1) g_off[NNODES] = off + pdeg;
}

// ---------------------------------------------------------------------------
// fill CSR + init S0 = dis*x; TWO edges / float4-slots per thread for MLP.
__global__ void fill_init_kernel(const void* __restrict__ eiv,
                                 const float4* __restrict__ x4) {
    int t = blockIdx.x * blockDim.x + threadIdx.x;
    int e0 = 2 * t;
    if (e0 >= NEDGES) return;

    int s0, s1, d0, d1;
    if (g_idx64) {
        const longlong2* ps = (const longlong2*)eiv;
        longlong2 sp = __ldg(&ps[t]);                     // src[e0], src[e0+1]
        longlong2 dp = __ldg(&ps[(NEDGES >> 1) + t]);     // dst[e0], dst[e0+1]
        s0 = (int)sp.x; s1 = (int)sp.y;
        d0 = (int)dp.x; d1 = (int)dp.y;
    } else {
        const int2* ps = (const int2*)eiv;
        int2 sp = __ldg(&ps[t]);
        int2 dp = __ldg(&ps[(NEDGES >> 1) + t]);
        s0 = sp.x; s1 = sp.y;
        d0 = dp.x; d1 = dp.y;
    }
    int p0 = atomicAdd(&g_cursor[d0], 1);
    g_csr[p0] = s0;
    int p1 = atomicAdd(&g_cursor[d1], 1);
    g_csr[p1] = s1;

    // feature init: slots e0, e0+1 (same 16-slot row unless crossing at e0&15==15;
    // compute nodes independently — adjacent, mostly identical dis)
    int n0 = e0 >> 4, n1 = (e0 + 1) >> 4;
    float dis0 = __ldg(&g_dis[n0]);
    float dis1 = (n1 == n0) ? dis0 : __ldg(&g_dis[n1]);
    float4 v0 = __ldg(&x4[e0]);
    float4 v1 = __ldg(&x4[e0 + 1]);
    g_feat[0][2 * e0]     = __floats2half2_rn(dis0 * v0.x, dis0 * v0.y);
    g_feat[0][2 * e0 + 1] = __floats2half2_rn(dis0 * v0.z, dis0 * v0.w);
    g_feat[0][2 * e0 + 2] = __floats2half2_rn(dis1 * v1.x, dis1 * v1.y);
    g_feat[0][2 * e0 + 3] = __floats2half2_rn(dis1 * v1.z, dis1 * v1.w);
}

// ---------------------------------------------------------------------------
// Gather core: 8 lanes/node, 16 B/lane, uniform 4-edge bodies, csr quad
// prefetched one body ahead (breaks csr->rows serial chain across bodies).
__device__ __forceinline__ void acc_row(float2& a0, float2& a1, float2& a2, float2& a3,
                                        uint4 r) {
    float2 f0 = __half22float2(*reinterpret_cast<__half2*>(&r.x));
    float2 f1 = __half22float2(*reinterpret_cast<__half2*>(&r.y));
    float2 f2 = __half22float2(*reinterpret_cast<__half2*>(&r.z));
    float2 f3 = __half22float2(*reinterpret_cast<__half2*>(&r.w));
    a0.x += f0.x; a0.y += f0.y;
    a1.x += f1.x; a1.y += f1.y;
    a2.x += f2.x; a2.y += f2.y;
    a3.x += f3.x; a3.y += f3.y;
}

__device__ __forceinline__ void gather_accum(int node, int sl,
                                             const uint4* __restrict__ fp,
                                             float2& a0, float2& a1,
                                             float2& a2, float2& a3) {
    int beg = __ldg(&g_off[node]), end = __ldg(&g_off[node + 1]);
    a0 = {0.f, 0.f}; a1 = {0.f, 0.f}; a2 = {0.f, 0.f}; a3 = {0.f, 0.f};

    const int4* c4 = reinterpret_cast<const int4*>(g_csr);
    int jq = beg >> 2, nq = (end - beg) >> 2;
    if (nq <= 0) return;

    int4 c = __ldg(&c4[jq]);
    for (int b = 1; b < nq; b++) {
        int4 cn = __ldg(&c4[jq + b]);          // prefetch next quad
        uint4 r0 = __ldg(&fp[c.x * 8 + sl]);
        uint4 r1 = __ldg(&fp[c.y * 8 + sl]);
        uint4 r2 = __ldg(&fp[c.z * 8 + sl]);
        uint4 r3 = __ldg(&fp[c.w * 8 + sl]);
        acc_row(a0, a1, a2, a3, r0);
        acc_row(a0, a1, a2, a3, r1);
        acc_row(a0, a1, a2, a3, r2);
        acc_row(a0, a1, a2, a3, r3);
        c = cn;
    }
    uint4 r0 = __ldg(&fp[c.x * 8 + sl]);
    uint4 r1 = __ldg(&fp[c.y * 8 + sl]);
    uint4 r2 = __ldg(&fp[c.z * 8 + sl]);
    uint4 r3 = __ldg(&fp[c.w * 8 + sl]);
    acc_row(a0, a1, a2, a3, r0);
    acc_row(a0, a1, a2, a3, r1);
    acc_row(a0, a1, a2, a3, r2);
    acc_row(a0, a1, a2, a3, r3);
}

// iterations k = 1..3: S_k = S_{k-1} - dis^2 * agg   (fp16 store)
__global__ void gather_kernel(int k) {
    int t = blockIdx.x * blockDim.x + threadIdx.x;
    int node = t >> 3;
    if (node >= NNODES) return;
    int sl = t & 7;

    const uint4* fp = reinterpret_cast<const uint4*>(g_feat[k - 1]);
    uint4*       fn = reinterpret_cast<uint4*>(g_feat[k]);

    float2 a0, a1, a2, a3;
    gather_accum(node, sl, fp, a0, a1, a2, a3);

    float d2 = __ldg(&g_dis2[node]);
    uint4 own = fp[node * 8 + sl];
    float2 f0 = __half22float2(*reinterpret_cast<__half2*>(&own.x));
    float2 f1 = __half22float2(*reinterpret_cast<__half2*>(&own.y));
    float2 f2 = __half22float2(*reinterpret_cast<__half2*>(&own.z));
    float2 f3 = __half22float2(*reinterpret_cast<__half2*>(&own.w));

    __half2 o0 = __floats2half2_rn(f0.x - d2 * a0.x, f0.y - d2 * a0.y);
    __half2 o1 = __floats2half2_rn(f1.x - d2 * a1.x, f1.y - d2 * a1.y);
    __half2 o2 = __floats2half2_rn(f2.x - d2 * a2.x, f2.y - d2 * a2.y);
    __half2 o3 = __floats2half2_rn(f3.x - d2 * a3.x, f3.y - d2 * a3.y);

    uint4 out;
    out.x = *reinterpret_cast<unsigned*>(&o0);
    out.y = *reinterpret_cast<unsigned*>(&o1);
    out.z = *reinterpret_cast<unsigned*>(&o2);
    out.w = *reinterpret_cast<unsigned*>(&o3);
    fn[node * 8 + sl] = out;
}

// iteration k = 4 fused with the polynomial combine:
// out = 0.6*x + invdis * (-0.4*S1 + 0.3*S2 - 0.2*S3 + 0.1*S4),  S4 = S3 - dis^2*agg
__global__ void gather_final_kernel(const float4* __restrict__ x4,
                                    float4* __restrict__ out4) {
    int t = blockIdx.x * blockDim.x + threadIdx.x;
    int node = t >> 3;
    if (node >= NNODES) return;
    int sl = t & 7;

    const uint4* fp3 = reinterpret_cast<const uint4*>(g_feat[3]);

    float2 a0, a1, a2, a3;
    gather_accum(node, sl, fp3, a0, a1, a2, a3);

    float d2 = __ldg(&g_dis2[node]);
    float inv = __ldg(&g_invdis[node]);
    int ri = node * 8 + sl;

    uint4 r3 = fp3[ri];
    uint4 r1 = reinterpret_cast<const uint4*>(g_feat[1])[ri];
    uint4 r2 = reinterpret_cast<const uint4*>(g_feat[2])[ri];

    float agg[8] = {a0.x, a0.y, a1.x, a1.y, a2.x, a2.y, a3.x, a3.y};
    unsigned w3[4] = {r3.x, r3.y, r3.z, r3.w};
    unsigned w1[4] = {r1.x, r1.y, r1.z, r1.w};
    unsigned w2[4] = {r2.x, r2.y, r2.z, r2.w};

    float4 xv0 = __ldg(&x4[node * 16 + sl * 2]);
    float4 xv1 = __ldg(&x4[node * 16 + sl * 2 + 1]);
    float xs[8] = {xv0.x, xv0.y, xv0.z, xv0.w, xv1.x, xv1.y, xv1.z, xv1.w};

    float os[8];
#pragma unroll
    for (int q = 0; q < 4; q++) {
        float2 s3 = __half22float2(*reinterpret_cast<__half2*>(&w3[q]));
        float2 s1 = __half22float2(*reinterpret_cast<__half2*>(&w1[q]));
        float2 s2 = __half22float2(*reinterpret_cast<__half2*>(&w2[q]));
        float s4x = s3.x - d2 * agg[2 * q];
        float s4y = s3.y - d2 * agg[2 * q + 1];
        float px = fmaf(0.1f, s4x, fmaf(-0.2f, s3.x, fmaf(0.3f, s2.x, -0.4f * s1.x)));
        float py = fmaf(0.1f, s4y, fmaf(-0.2f, s3.y, fmaf(0.3f, s2.y, -0.4f * s1.y)));
        os[2 * q]     = fmaf(inv, px, 0.6f * xs[2 * q]);
        os[2 * q + 1] = fmaf(inv, py, 0.6f * xs[2 * q + 1]);
    }
    float4 o0 = {os[0], os[1], os[2], os[3]};
    float4 o1 = {os[4], os[5], os[6], os[7]};
    out4[node * 16 + sl * 2]     = o0;
    out4[node * 16 + sl * 2 + 1] = o1;
}

// ---------------------------------------------------------------------------
extern "C" void kernel_launch(void* const* d_in, const int* in_sizes, int n_in,
                              void* d_out, int out_size) {
    const float4* x4 = (const float4*)d_in[0];
    const void*   ei = d_in[1];

    detect_kernel<<<1, 256>>>((const int*)ei);
    deg_kernel<<<(NEDGES + 255) / 256, 256>>>(ei);
    scan_kernel<<<NBLK, 512>>>();
    fill_init_kernel<<<(NEDGES / 2 + 255) / 256, 256>>>(ei, x4);

    const int gthreads = NNODES * 8;
    const int gblocks = (gthreads + 255) / 256;
    for (int k = 1; k <= 3; k++)
        gather_kernel<<<gblocks, 256>>>(k);
    gather_final_kernel<<<gblocks, 256>>>(x4, (float4*)d_out);
}